// round 7
// baseline (speedup 1.0000x reference)
#include <cuda_runtime.h>
#include <math.h>

#define C        144
#define W        77
#define KW       10
#define FC       64
#define CONV_OUT 68                    // W - KW + 1
#define CONCAT   (C*FC + CONV_OUT)     // 9284
#define H2       128
#define NSPLIT   2                     // blocks per channel
#define HFC      (FC / NSPLIT)         // 32 FC cols per block
#define GRID     (C * NSPLIT)          // 288 blocks -> 2 per SM
#define NT       512                   // 16 warps per block

// Scratch (no device allocation allowed); zeroed at load, reset by last block.
__device__ __align__(16) float g_h[H2];
__device__ __align__(16) float g_conv[CONV_OUT];
__device__ unsigned int g_cnt = 0u;

__device__ __forceinline__ float warp_reduce(float v) {
#pragma unroll
    for (int o = 16; o > 0; o >>= 1) v += __shfl_down_sync(0xffffffffu, v, o);
    return v;
}

__device__ __forceinline__ float red4(float s) {     // reduce over 4-lane group
    s += __shfl_down_sync(0xffffffffu, s, 2, 4);
    s += __shfl_down_sync(0xffffffffu, s, 1, 4);
    return s;
}

__device__ __forceinline__ float dot4(float4 a, float4 b) {
    return a.x * b.x + a.y * b.y + a.z * b.z + a.w * b.w;
}

// ---------------------------------------------------------------------------
// Barrier-free fused kernel: 288 blocks x 512 threads (2 blocks per SM).
//   Block (c, half): computes 32 FC outputs of channel c (cols half*32..+32)
//     and accumulates g_h[j] += w2[j, c*64+half*32 : +32] . fc_vals.
//     half==0 blocks also add channel c's conv correlation into g_conv[68].
//   Last block (atomic counter): conv matvec (128x68, once) + final layers,
//   then resets all scratch for the next graph replay.
// ---------------------------------------------------------------------------
__global__ __launch_bounds__(NT, 2) void fused_kernel(
    const float* __restrict__ x,       // [C, W]
    const float* __restrict__ fc_w,    // [C, FC, W]
    const float* __restrict__ fc_b,    // [C, FC]
    const float* __restrict__ conv_w,  // [C, KW]
    const float* __restrict__ conv_b,  // [1]
    const float* __restrict__ w2,      // [H2, CONCAT]
    const float* __restrict__ b2,      // [H2]
    const float* __restrict__ w3,      // [1, H2]
    const float* __restrict__ b3,      // [1]
    float* __restrict__ out)           // [1]
{
    const int tid  = threadIdx.x;
    const int lane = tid & 31;
    const int warp = tid >> 5;
    const int c    = blockIdx.x >> 1;
    const int half = blockIdx.x & 1;

    const int j = tid >> 2;            // 0..127 : w2 row owned by this thread
    const int p = tid & 3;             // 0..3   : position within row group

    __shared__ float xs[W];
    __shared__ float cw[KW];
    __shared__ __align__(16) float vals[HFC];
    __shared__ __align__(16) float convv[CONV_OUT];
    __shared__ float sm_h[H2];
    __shared__ unsigned int s_last;

    // ---- stage 0: x row (+ conv weights for half==0) into smem ----
    if (tid < W)            xs[tid]     = x[c * W + tid];
    else if (tid < W + KW)  cw[tid - W] = conv_w[c * KW + (tid - W)];

    // ---- stage 1: front-batch this thread's w2 FC half-slice ----
    // row j, cols [c*64 + half*32, +32) = 8 float4; 4 threads/row, 2 each.
    const float4* wrow = reinterpret_cast<const float4*>(
        w2 + (size_t)j * CONCAT + c * FC + half * HFC);
    const float4 a0 = wrow[p];
    const float4 a1 = wrow[p + 4];

    __syncthreads();

    // ---- stage 2: conv contribution (half==0 blocks only) ----
    if (half == 0 && tid < CONV_OUT) {
        float s = 0.f;
#pragma unroll
        for (int k = 0; k < KW; k++) s += xs[tid + k] * cw[k];
        atomicAdd(&g_conv[tid], s);
    }

    // ---- stage 3: FC -- 16 warps x 2 outputs, warp-reduced dots ----
#pragma unroll
    for (int i = 0; i < 2; i++) {
        const int d = warp * 2 + i;                      // 0..31 local
        const int g = c * FC + half * HFC + d;           // global fc column
        const float* row = fc_w + (size_t)g * W;
        float s = row[lane] * xs[lane] + row[lane + 32] * xs[lane + 32];
        if (lane < W - 64)                               // 13 tail elements
            s += row[lane + 64] * xs[lane + 64];
        s = warp_reduce(s);
        if (lane == 0) vals[d] = s + fc_b[g];
    }
    __syncthreads();

    // ---- stage 4: g_h[j] += w2_slice[j,:] . vals ----
    {
        const float4* v4 = reinterpret_cast<const float4*>(vals);
        float s = dot4(a0, v4[p]) + dot4(a1, v4[p + 4]);
        s = red4(s);
        if (p == 0) atomicAdd(&g_h[j], s);
    }

    // ---- last-block election (no spinning; non-last blocks exit) ----
    if (p == 0 || (half == 0 && tid < CONV_OUT))
        __threadfence();             // release my REDs before my arrive
    __syncthreads();
    if (tid == 0)
        s_last = (atomicAdd(&g_cnt, 1u) == GRID - 1) ? 1u : 0u;
    __syncthreads();
    if (s_last == 0u) return;

    // =================== finalization (last block only) ===================
    __threadfence();                 // acquire all g_h / g_conv updates

    if (tid < CONV_OUT) {
        convv[tid]  = g_conv[tid] + conv_b[0];
        g_conv[tid] = 0.f;           // reset for next replay
    }
    __syncthreads();

    // conv matvec: h[j] += w2[j, 9216:9284] . convv ; then relu & w3 weight
    {
        const float4* rw = reinterpret_cast<const float4*>(
            w2 + (size_t)j * CONCAT + C * FC);           // 16B-aligned
        const float4* cv = reinterpret_cast<const float4*>(convv);
        float s = dot4(rw[p], cv[p]) + dot4(rw[p + 4], cv[p + 4])
                + dot4(rw[p + 8], cv[p + 8]) + dot4(rw[p + 12], cv[p + 12]);
        if (p == 0) s += dot4(rw[16], cv[16]);           // 17th float4
        s = red4(s);
        if (p == 0) {
            const float pre = g_h[j] + s + b2[j];
            sm_h[j] = fmaxf(pre, 0.f) * w3[j];
            g_h[j]  = 0.f;           // reset for next replay
        }
    }
    __syncthreads();

    if (warp == 0) {
        float v = sm_h[lane] + sm_h[lane + 32]
                + sm_h[lane + 64] + sm_h[lane + 96];
        v = warp_reduce(v);
        if (lane == 0) {
            const float o2 = fmaxf(v + b3[0], 0.f);
            out[0] = 1.f / (1.f + __expf(-o2));
            g_cnt  = 0u;             // reset for next replay
        }
    }
}

// ---------------------------------------------------------------------------
extern "C" void kernel_launch(void* const* d_in, const int* in_sizes, int n_in,
                              void* d_out, int out_size) {
    const float* x      = (const float*)d_in[0];
    const float* fc_w   = (const float*)d_in[1];
    const float* fc_b   = (const float*)d_in[2];
    const float* conv_w = (const float*)d_in[3];
    const float* conv_b = (const float*)d_in[4];
    const float* w2     = (const float*)d_in[5];
    const float* b2     = (const float*)d_in[6];
    const float* w3     = (const float*)d_in[7];
    const float* b3     = (const float*)d_in[8];

    fused_kernel<<<GRID, NT>>>(x, fc_w, fc_b, conv_w, conv_b,
                               w2, b2, w3, b3, (float*)d_out);
}

// round 8
// speedup vs baseline: 1.0239x; 1.0239x over previous
#include <cuda_runtime.h>
#include <math.h>

#define C        144
#define W        77
#define KW       10
#define FC       64
#define CONV_OUT 68                    // W - KW + 1
#define CONCAT   (C*FC + CONV_OUT)     // 9284
#define H2       128
#define GRID     C                     // one block per channel, 1 per SM
#define NT       1024                  // 32 warps per block
#define PAD      64                    // 64 floats = 256 B accumulator stride
                                       // -> spreads atomics across ~64 L2 slices

// Scratch (no device allocation allowed); zeroed at load, reset by last block.
// PADDED: one accumulator per 256 B so the L2 slice hash (bits {8,10-27})
// distributes the atomic traffic instead of funneling it into ~2 slices.
__device__ __align__(256) float g_hp[H2 * PAD];          // 32 KB
__device__ __align__(256) float g_convp[CONV_OUT * PAD]; // 17 KB
__device__ unsigned int g_cnt = 0u;

__device__ __forceinline__ float warp_reduce(float v) {
#pragma unroll
    for (int o = 16; o > 0; o >>= 1) v += __shfl_down_sync(0xffffffffu, v, o);
    return v;
}

__device__ __forceinline__ float dot4(float4 a, float4 b) {
    return a.x * b.x + a.y * b.y + a.z * b.z + a.w * b.w;
}

// ---------------------------------------------------------------------------
// Barrier-free fused kernel, one 1024-thread block per channel.
//   Block c:
//     - preload w2[:, c*64:(c+1)*64] into registers (2 float4/thread, 8 th/row)
//     - FC: 64 outputs (32 warps x 2 outputs, warp-reduced dots, x in smem)
//     - conv: channel c's contribution -> RED into padded g_convp
//     - g_hp[j*PAD] += w2_slice[j,:] . fc_vals  (8-lane reduce + RED)
//   Last block (atomic counter): conv matvec (128x68, once) + final layers,
//   then resets all scratch for the next graph replay.
// ---------------------------------------------------------------------------
__global__ __launch_bounds__(NT, 1) void fused_kernel(
    const float* __restrict__ x,       // [C, W]
    const float* __restrict__ fc_w,    // [C, FC, W]
    const float* __restrict__ fc_b,    // [C, FC]
    const float* __restrict__ conv_w,  // [C, KW]
    const float* __restrict__ conv_b,  // [1]
    const float* __restrict__ w2,      // [H2, CONCAT]
    const float* __restrict__ b2,      // [H2]
    const float* __restrict__ w3,      // [1, H2]
    const float* __restrict__ b3,      // [1]
    float* __restrict__ out)           // [1]
{
    const int tid  = threadIdx.x;
    const int lane = tid & 31;
    const int warp = tid >> 5;
    const int c    = blockIdx.x;

    const int j = tid >> 3;            // 0..127 : w2 row owned by this thread
    const int p = tid & 7;             // 0..7   : position within row group

    __shared__ float xs[W];
    __shared__ float cw[KW];
    __shared__ __align__(16) float vals[FC];
    __shared__ __align__(16) float convv[CONV_OUT];
    __shared__ float sm_h[H2];
    __shared__ unsigned int s_last;

    // ---- stage 0: x row + conv weights into smem ----
    if (tid < W)               xs[tid]     = x[c * W + tid];
    else if (tid < W + KW)     cw[tid - W] = conv_w[c * KW + (tid - W)];

    // ---- stage 1: front-batch this thread's w2 FC slice (max MLP) ----
    // row j cols [c*64, c*64+64) = 16 float4; 8 threads/row, 2 each.
    const float4* wrow = reinterpret_cast<const float4*>(
        w2 + (size_t)j * CONCAT + c * FC);
    const float4 a0 = wrow[p];
    const float4 a1 = wrow[p + 8];

    __syncthreads();

    // ---- stage 2: conv contribution of channel c (padded RED) ----
    if (tid < CONV_OUT) {
        float s = 0.f;
#pragma unroll
        for (int k = 0; k < KW; k++) s += xs[tid + k] * cw[k];
        atomicAdd(&g_convp[tid * PAD], s);
    }

    // ---- stage 3: FC -- 32 warps x 2 outputs, warp-reduced dots ----
#pragma unroll
    for (int i = 0; i < 2; i++) {
        const int d = warp * 2 + i;                      // 0..63
        const float* row = fc_w + (size_t)(c * FC + d) * W;
        float s = row[lane] * xs[lane] + row[lane + 32] * xs[lane + 32];
        if (lane < W - 64)                               // 13 tail elements
            s += row[lane + 64] * xs[lane + 64];
        s = warp_reduce(s);
        if (lane == 0) vals[d] = s + fc_b[c * FC + d];
    }
    __syncthreads();

    // ---- stage 4: g_hp[j*PAD] += w2_slice[j,:] . vals (padded RED) ----
    {
        const float4* v4 = reinterpret_cast<const float4*>(vals);
        float s = dot4(a0, v4[p]) + dot4(a1, v4[p + 8]);
#pragma unroll
        for (int o = 4; o > 0; o >>= 1)
            s += __shfl_down_sync(0xffffffffu, s, o, 8);
        if (p == 0) {
            atomicAdd(&g_hp[j * PAD], s);
            __threadfence();         // release my RED before my arrive
        }
    }

    // ---- last-block election (no spinning; non-last blocks exit) ----
    __syncthreads();
    if (tid == 0)
        s_last = (atomicAdd(&g_cnt, 1u) == GRID - 1) ? 1u : 0u;
    __syncthreads();
    if (s_last == 0u) return;

    // =================== finalization (last block only) ===================
    __threadfence();                 // acquire all g_hp / g_convp updates

    if (tid < CONV_OUT) {
        convv[tid]          = g_convp[tid * PAD] + conv_b[0];
        g_convp[tid * PAD]  = 0.f;   // reset for next replay
    }
    __syncthreads();

    // conv matvec: h[j] += w2[j, 9216:9284] . convv ; then relu & w3 weight
    {
        const float4* rw = reinterpret_cast<const float4*>(
            w2 + (size_t)j * CONCAT + C * FC);           // 16B-aligned
        const float4* cv = reinterpret_cast<const float4*>(convv);
        float s = dot4(rw[p], cv[p]) + dot4(rw[p + 8], cv[p + 8]);
        if (p == 0) s += dot4(rw[16], cv[16]);           // 17th float4
#pragma unroll
        for (int o = 4; o > 0; o >>= 1)
            s += __shfl_down_sync(0xffffffffu, s, o, 8);
        if (p == 0) {
            const float pre = g_hp[j * PAD] + s + b2[j];
            sm_h[j] = fmaxf(pre, 0.f) * w3[j];
            g_hp[j * PAD] = 0.f;     // reset for next replay
        }
    }
    __syncthreads();

    if (warp == 0) {
        float v = sm_h[lane] + sm_h[lane + 32]
                + sm_h[lane + 64] + sm_h[lane + 96];
        v = warp_reduce(v);
        if (lane == 0) {
            const float o2 = fmaxf(v + b3[0], 0.f);
            out[0] = 1.f / (1.f + __expf(-o2));
            g_cnt  = 0u;             // reset for next replay
        }
    }
}

// ---------------------------------------------------------------------------
extern "C" void kernel_launch(void* const* d_in, const int* in_sizes, int n_in,
                              void* d_out, int out_size) {
    const float* x      = (const float*)d_in[0];
    const float* fc_w   = (const float*)d_in[1];
    const float* fc_b   = (const float*)d_in[2];
    const float* conv_w = (const float*)d_in[3];
    const float* conv_b = (const float*)d_in[4];
    const float* w2     = (const float*)d_in[5];
    const float* b2     = (const float*)d_in[6];
    const float* w3     = (const float*)d_in[7];
    const float* b3     = (const float*)d_in[8];

    fused_kernel<<<GRID, NT>>>(x, fc_w, fc_b, conv_w, conv_b,
                               w2, b2, w3, b3, (float*)d_out);
}